// round 13
// baseline (speedup 1.0000x reference)
#include <cuda_runtime.h>
#include <cuda_bf16.h>

#define NCTA   148
#define WPB    32
#define B_     32
#define C_     768
#define CR_    192
#define BC_    24576
#define NMLP   192            // mlp warps: warp31 of all CTAs + warp30 of CTAs<44
#define NPOOL  1824
#define NSCALE 2720           // NPOOL+NSCALE = 148*30+104 = 4544

// Scratch + flow-control state. All counters return to 0 each launch (last
// scale warp resets) -> safe across CUDA-graph replays.
__device__ float    d_s[BC_];
__device__ float    d_h[B_ * CR_];
__device__ unsigned cnt[B_];     // pooled channels per batch (0..768)
__device__ unsigned hdone[B_];   // finished h-dots per batch (0..192)
__device__ unsigned sdone;       // scale warp completion tickets

struct F8 { float a0,a1,a2,a3,a4,a5,a6,a7; };
__device__ __forceinline__ F8 ld_evict_last_32B(const void* p) {
    F8 v;
    asm volatile(
        "ld.global.L2::evict_last.v8.b32 {%0,%1,%2,%3,%4,%5,%6,%7}, [%8];"
        : "=f"(v.a0), "=f"(v.a1), "=f"(v.a2), "=f"(v.a3),
          "=f"(v.a4), "=f"(v.a5), "=f"(v.a6), "=f"(v.a7)
        : "l"(p));
    return v;
}

__global__ __launch_bounds__(1024, 1)
void se_pipeline(const float* __restrict__ x,
                 const float* __restrict__ w1,
                 const float* __restrict__ b1,
                 const float* __restrict__ w2,
                 const float* __restrict__ b2,
                 float* __restrict__ out) {
    int tid  = threadIdx.x;
    int warp = tid >> 5;
    int lane = tid & 31;
    int bid  = blockIdx.x;

    // ---------------- Role: MLP (192 warps, one per w1 row) -----------------
    bool is_mlp = (warp == 31) || (warp == 30 && bid < 44);
    if (is_mlp) {
        int j = (warp == 31) ? bid : (148 + bid);        // 0..191
        const float* wr = w1 + (size_t)j * C_;           // row reused 32x (L1)
        for (int b = 0; b < B_; b++) {
            if (lane == 0)
                while (*(volatile unsigned*)&cnt[b] < 768u) __nanosleep(64);
            __syncwarp();
            __threadfence();                             // acquire d_s[b]
            const float* sr = d_s + b * C_;
            float acc = 0.0f;
#pragma unroll
            for (int t = 0; t < 24; t++) { int k = lane + t * 32; acc += sr[k] * wr[k]; }
#pragma unroll
            for (int o = 16; o; o >>= 1) acc += __shfl_xor_sync(0xffffffffu, acc, o);
            if (lane == 0) {
                float h = acc + b1[j];
                d_h[b * CR_ + j] = h / (1.0f + __expf(-h));
                __threadfence();                         // release d_h before flag
                atomicAdd(&hdone[b], 1);
            }
        }
        return;
    }

    // linear rank among the 4544 non-mlp warps
    int r = (warp < 30) ? (bid * 30 + warp) : (4440 + (bid - 44));

    if (r < NPOOL) {
        // ---------------- Role: POOL (never waits; batches ascend) ----------
        for (int ch = r; ch < BC_; ch += NPOOL) {
            const char* base = reinterpret_cast<const char*>(x) + (size_t)ch * 4096;
            float sum = 0.0f;
#pragma unroll
            for (int i = 0; i < 4; i++) {
                F8 v = ld_evict_last_32B(base + (lane + i * 32) * 32);
                sum += ((v.a0 + v.a1) + (v.a2 + v.a3)) + ((v.a4 + v.a5) + (v.a6 + v.a7));
            }
#pragma unroll
            for (int o = 16; o; o >>= 1) sum += __shfl_xor_sync(0xffffffffu, sum, o);
            if (lane == 0) {
                d_s[ch] = sum * (1.0f / 1024.0f);
                __threadfence();                         // release d_s before count
                atomicAdd(&cnt[ch / C_], 1);
            }
        }
    } else {
        // ---------------- Role: SCALE (trails pool by ~1-3 batches) ---------
        int i = r - NPOOL;                               // 0..2719
        for (int ch = i; ch < BC_; ch += NSCALE) {
            int b = ch / C_;
            int c = ch - b * C_;
            if (lane == 0)
                while (*(volatile unsigned*)&hdone[b] < 192u) __nanosleep(64);
            __syncwarp();
            __threadfence();                             // acquire d_h[b]

            // gate: all lanes end with the full sum via butterfly reduce
            const float* hr = d_h + b * CR_;
            const float* wr = w2 + (size_t)c * CR_;
            float acc = 0.0f;
#pragma unroll
            for (int t = 0; t < 6; t++) { int k = lane + t * 32; acc += hr[k] * wr[k]; }
#pragma unroll
            for (int o = 16; o; o >>= 1) acc += __shfl_xor_sync(0xffffffffu, acc, o);
            float g = 1.0f / (1.0f + __expf(-(acc + b2[c])));

            const float4* p = reinterpret_cast<const float4*>(x) + (size_t)ch * 256;
            float4*       q = reinterpret_cast<float4*>(out) + (size_t)ch * 256;
#pragma unroll
            for (int j = 0; j < 8; j++) {
                float4 v = __ldcs(p + lane + j * 32);    // L2-hot: recent pool
                v.x *= g; v.y *= g; v.z *= g; v.w *= g;
                __stcs(q + lane + j * 32, v);
            }
        }
        // ticket; last scale warp resets all flow-control state for replay
        if (lane == 0) {
            __threadfence();
            if (atomicAdd(&sdone, 1) == NSCALE - 1) {
#pragma unroll
                for (int b = 0; b < B_; b++) { cnt[b] = 0; hdone[b] = 0; }
                __threadfence();
                sdone = 0;
            }
        }
    }
}

// ---------------------------------------------------------------------------
extern "C" void kernel_launch(void* const* d_in, const int* in_sizes, int n_in,
                              void* d_out, int out_size) {
    const float* x  = (const float*)d_in[0];
    const float* w1 = (const float*)d_in[1];
    const float* b1 = (const float*)d_in[2];
    const float* w2 = (const float*)d_in[3];
    const float* b2 = (const float*)d_in[4];
    float* out = (float*)d_out;

    se_pipeline<<<NCTA, 1024>>>(x, w1, b1, w2, b2, out);
}

// round 14
// speedup vs baseline: 2.1091x; 2.1091x over previous
#include <cuda_runtime.h>
#include <cuda_bf16.h>

#define B_     32
#define C_     768
#define CR_    192
#define BC_    24576
#define HALFCH 12288          // channels per half (16 batches)
#define HALFD  3072           // h-dots per half (16 * 192)
#define MCTA   384            // mlp CTAs per half (8 warp-dots each)

// Scratch (device globals)
__device__ float d_s[BC_];
__device__ float d_h[B_ * CR_];

struct F8 { float a0,a1,a2,a3,a4,a5,a6,a7; };
__device__ __forceinline__ F8 ld_evict_last_32B(const void* p) {
    F8 v;
    asm volatile(
        "ld.global.L2::evict_last.v8.b32 {%0,%1,%2,%3,%4,%5,%6,%7}, [%8];"
        : "=f"(v.a0), "=f"(v.a1), "=f"(v.a2), "=f"(v.a3),
          "=f"(v.a4), "=f"(v.a5), "=f"(v.a6), "=f"(v.a7)
        : "l"(p));
    return v;
}

// ---- building blocks ------------------------------------------------------
__device__ __forceinline__ void pool_ch(const float* __restrict__ x, int ch, int lane) {
    const char* base = reinterpret_cast<const char*>(x) + (size_t)ch * 4096;
    float sum = 0.0f;
#pragma unroll
    for (int i = 0; i < 4; i++) {
        F8 v = ld_evict_last_32B(base + (lane + i * 32) * 32);
        sum += ((v.a0 + v.a1) + (v.a2 + v.a3)) + ((v.a4 + v.a5) + (v.a6 + v.a7));
    }
#pragma unroll
    for (int o = 16; o; o >>= 1) sum += __shfl_xor_sync(0xffffffffu, sum, o);
    if (lane == 0) d_s[ch] = sum * (1.0f / 1024.0f);
}

__device__ __forceinline__ void mlp_dot(const float* __restrict__ w1,
                                        const float* __restrict__ b1,
                                        int b, int j, int lane) {
    const float* wr = w1 + (size_t)j * C_;
    const float* sr = d_s + b * C_;
    float acc = 0.0f;
#pragma unroll
    for (int t = 0; t < 24; t++) { int k = lane + t * 32; acc += sr[k] * wr[k]; }
#pragma unroll
    for (int o = 16; o; o >>= 1) acc += __shfl_xor_sync(0xffffffffu, acc, o);
    if (lane == 0) {
        float h = acc + b1[j];
        d_h[b * CR_ + j] = h / (1.0f + __expf(-h));
    }
}

// ---- K1: pool half0 -------------------------------------------------------
__global__ __launch_bounds__(256) void k_pool0(const float* __restrict__ x) {
    int warp = threadIdx.x >> 5, lane = threadIdx.x & 31;
    pool_ch(x, blockIdx.x * 8 + warp, lane);
}

// ---- K2: mlp(half0) || pool half1 ----------------------------------------
__global__ __launch_bounds__(256) void k_mlp0_pool1(const float* __restrict__ x,
                                                    const float* __restrict__ w1,
                                                    const float* __restrict__ b1) {
    int warp = threadIdx.x >> 5, lane = threadIdx.x & 31;
    if (blockIdx.x < MCTA) {
        int gw = blockIdx.x * 8 + warp;          // 0..3071
        mlp_dot(w1, b1, gw / CR_, gw % CR_, lane);
    } else {
        pool_ch(x, HALFCH + (blockIdx.x - MCTA) * 8 + warp, lane);
    }
}

// ---- scale body: CTA per channel, gate in warp0 overlapped with x load ----
__device__ __forceinline__ void scale_ch(const float* __restrict__ x,
                                         const float* __restrict__ w2,
                                         const float* __restrict__ b2,
                                         float* __restrict__ out, int ch) {
    __shared__ float g_sm;
    int tid = threadIdx.x;
    const float4* xp = reinterpret_cast<const float4*>(x) + (size_t)ch * 256 + tid;
    float4 v = __ldcs(xp);                       // independent; issues first

    if (tid < 32) {
        int c = ch % C_;
        int b = ch / C_;
        const float* wr = w2 + (size_t)c * CR_;
        const float* hr = d_h + b * CR_;
        float acc = 0.0f;
#pragma unroll
        for (int t = 0; t < 6; t++) { int k = tid + t * 32; acc += hr[k] * wr[k]; }
#pragma unroll
        for (int o = 16; o; o >>= 1) acc += __shfl_xor_sync(0xffffffffu, acc, o);
        if (tid == 0) g_sm = 1.0f / (1.0f + __expf(-(acc + b2[c])));
    }
    __syncthreads();

    float g = g_sm;
    v.x *= g; v.y *= g; v.z *= g; v.w *= g;
    __stcs(reinterpret_cast<float4*>(out) + (size_t)ch * 256 + tid, v);
}

// ---- K3: mlp(half1) || scale half0 ---------------------------------------
__global__ __launch_bounds__(256) void k_mlp1_scale0(const float* __restrict__ x,
                                                     const float* __restrict__ w1,
                                                     const float* __restrict__ b1,
                                                     const float* __restrict__ w2,
                                                     const float* __restrict__ b2,
                                                     float* __restrict__ out) {
    if (blockIdx.x < MCTA) {
        int warp = threadIdx.x >> 5, lane = threadIdx.x & 31;
        int gw = blockIdx.x * 8 + warp;          // 0..3071
        mlp_dot(w1, b1, 16 + gw / CR_, gw % CR_, lane);
    } else {
        scale_ch(x, w2, b2, out, blockIdx.x - MCTA);
    }
}

// ---- K4: scale half1 ------------------------------------------------------
__global__ __launch_bounds__(256) void k_scale1(const float* __restrict__ x,
                                                const float* __restrict__ w2,
                                                const float* __restrict__ b2,
                                                float* __restrict__ out) {
    scale_ch(x, w2, b2, out, HALFCH + blockIdx.x);
}

// ---------------------------------------------------------------------------
extern "C" void kernel_launch(void* const* d_in, const int* in_sizes, int n_in,
                              void* d_out, int out_size) {
    const float* x  = (const float*)d_in[0];
    const float* w1 = (const float*)d_in[1];
    const float* b1 = (const float*)d_in[2];
    const float* w2 = (const float*)d_in[3];
    const float* b2 = (const float*)d_in[4];
    float* out = (float*)d_out;

    k_pool0<<<HALFCH / 8, 256>>>(x);                              // 1536 CTAs
    k_mlp0_pool1<<<MCTA + HALFCH / 8, 256>>>(x, w1, b1);          // 1920 CTAs
    k_mlp1_scale0<<<MCTA + HALFCH, 256>>>(x, w1, b1, w2, b2, out);// 12672 CTAs
    k_scale1<<<HALFCH, 256>>>(x, w2, b2, out);                    // 12288 CTAs
}